// round 15
// baseline (speedup 1.0000x reference)
#include <cuda_runtime.h>
#include <cuda_bf16.h>

// InterAgg (FRAUDRE inter-relation aggregation), GB300 sm_103a.
//
// out[n] = [ self | relu(self) | sum_r relu(mean_j feat[nidx_r[n,j]]) * softmax(alpha)[64:,r] ]
// (softmax rows sum to 1 => aggregated first half == relu(self) exactly)
//
// R14: R13 core (one warp/node, float2 lanes, coalesced 256B row gathers,
// streaming ldcs/stcs on single-touch index/output streams) with 64-thread
// CTAs (2 warps, 4096 CTAs). At 1024x8-warp CTAs the single-wave residency
// split 6 vs 7 CTAs/SM (48 vs 56 warps, 16% imbalance); since the kernel is
// DRAM-demand-limited (busy only 68%), the light SMs drain early and the
// tail runs under-demanded. 2-warp CTAs cut the imbalance to ~4%.

#define NB 8192
#define DEG 32
#define ED 64

__device__ __forceinline__ void softmax3(float& a, float& b, float& c) {
    float m = fmaxf(a, fmaxf(b, c));
    float e0 = __expf(a - m);
    float e1 = __expf(b - m);
    float e2 = __expf(c - m);
    float inv = __frcp_rn(e0 + e1 + e2);
    a = e0 * inv; b = e1 * inv; c = e2 * inv;
}

__global__ __launch_bounds__(64)
void interagg_kernel(const float2* __restrict__ feat2,   // features as float2[NUM_NODES*32]
                     const float*  __restrict__ alpha,   // (128, 3)
                     const int*    __restrict__ nodes,   // (NB,)
                     const int*    __restrict__ n1,      // (NB, DEG)
                     const int*    __restrict__ n2,
                     const int*    __restrict__ n3,
                     float*        __restrict__ out)     // (NB, 192)
{
    const int w    = (blockIdx.x * blockDim.x + threadIdx.x) >> 5;
    const int lane = threadIdx.x & 31;
    if (w >= NB) return;

    // --- index loads (coalesced, streaming: read-once per iteration) ---
    const int node = __ldcs(&nodes[w]);
    const int base = w * DEG + lane;
    const int i1 = __ldcs(&n1[base]);
    const int i2 = __ldcs(&n2[base]);
    const int i3 = __ldcs(&n3[base]);

    // --- self row gather: lane l reads float2 at dims {2l,2l+1} ---
    const float2 s = __ldg(&feat2[node * 32 + lane]);

    // --- neighbor gathers: 96 coalesced 256B row reads per warp ---
    float2 a1 = make_float2(0.f, 0.f);
    float2 a2 = make_float2(0.f, 0.f);
    float2 a3 = make_float2(0.f, 0.f);

#pragma unroll
    for (int j = 0; j < DEG; j++) {
        const int x1 = __shfl_sync(0xffffffffu, i1, j);
        const int x2 = __shfl_sync(0xffffffffu, i2, j);
        const int x3 = __shfl_sync(0xffffffffu, i3, j);
        const float2 v1 = __ldg(&feat2[x1 * 32 + lane]);
        const float2 v2 = __ldg(&feat2[x2 * 32 + lane]);
        const float2 v3 = __ldg(&feat2[x3 * 32 + lane]);
        a1.x += v1.x; a1.y += v1.y;
        a2.x += v2.x; a2.y += v2.y;
        a3.x += v3.x; a3.y += v3.y;
    }

    // --- per-dim softmax weights, agg half only (alpha rows 64+2l, 65+2l) ---
    const int r0 = (ED + 2 * lane) * 3;
    float w00 = __ldg(&alpha[r0 + 0]), w01 = __ldg(&alpha[r0 + 1]), w02 = __ldg(&alpha[r0 + 2]);
    float w10 = __ldg(&alpha[r0 + 3]), w11 = __ldg(&alpha[r0 + 4]), w12 = __ldg(&alpha[r0 + 5]);
    softmax3(w00, w01, w02);
    softmax3(w10, w11, w12);

    const float inv = 1.0f / (float)DEG;
    const float g1x = fmaxf(a1.x * inv, 0.f), g1y = fmaxf(a1.y * inv, 0.f);
    const float g2x = fmaxf(a2.x * inv, 0.f), g2y = fmaxf(a2.y * inv, 0.f);
    const float g3x = fmaxf(a3.x * inv, 0.f), g3y = fmaxf(a3.y * inv, 0.f);

    const float ox = g1x * w00 + g2x * w01 + g3x * w02;
    const float oy = g1y * w10 + g2y * w11 + g3y * w12;

    // --- write 192 floats: [self | relu(self) | weighted agg], streaming ---
    float* ob = out + (size_t)w * 192;
    __stcs(&reinterpret_cast<float2*>(ob)[lane], s);
    __stcs(&reinterpret_cast<float2*>(ob + 64)[lane],
           make_float2(fmaxf(s.x, 0.f), fmaxf(s.y, 0.f)));
    __stcs(&reinterpret_cast<float2*>(ob + 128)[lane], make_float2(ox, oy));
}

extern "C" void kernel_launch(void* const* d_in, const int* in_sizes, int n_in,
                              void* d_out, int out_size) {
    const float2* feat2 = (const float2*)d_in[0];
    const float*  alpha = (const float*)d_in[1];
    const int*    nodes = (const int*)d_in[2];
    const int*    n1    = (const int*)d_in[3];
    const int*    n2    = (const int*)d_in[4];
    const int*    n3    = (const int*)d_in[5];
    float*        out   = (float*)d_out;

    const int threads = 64;                                 // 2 warps = 2 nodes / CTA
    const int blocks  = (NB * 32 + threads - 1) / threads;  // 4096
    interagg_kernel<<<blocks, threads>>>(feat2, alpha, nodes, n1, n2, n3, out);
}